// round 16
// baseline (speedup 1.0000x reference)
#include <cuda_runtime.h>
#include <math.h>

#define T_SEQ 8192
#define HDIM  1024
#define NBLK  128     // scan CTAs (<=148 SMs -> all co-resident at 1 CTA/SM)

typedef unsigned long long u64;

// ---------------- static device scratch (no runtime allocation) ----------------
__device__ float           g_XP[3][T_SEQ * HDIM];   // xu, xr, xc projections
__device__ __align__(16) float g_hbuf[2][HDIM];     // double-buffered hidden state (fallback)
__device__ unsigned        g_cnt;                   // global barrier counter (fallback)
__device__ __align__(16) float g_pmin[NBLK][HDIM];  // per-CTA partial column mins of XPu
__device__ __align__(16) float g_h1[HDIM];          // h after step 0
__device__ int             g_fast;                  // 1 = saturation bound verified

// ---------------- Phase 1: C[z] = x @ U[z]^T + bias[z]  (fp32, NT) ----------------
__global__ __launch_bounds__(256) void proj_gemm(
    const float* __restrict__ x,
    const float* __restrict__ Uu, const float* __restrict__ Ur, const float* __restrict__ Uc,
    const float* __restrict__ Bu, const float* __restrict__ Br, const float* __restrict__ Bc)
{
    const int z = blockIdx.z;
    const float* __restrict__ Bmat = (z == 0) ? Uu : ((z == 1) ? Ur : Uc);
    const float* __restrict__ bias = (z == 0) ? Bu : ((z == 1) ? Br : Bc);
    float* __restrict__ C = g_XP[z];

    const int m0 = blockIdx.x * 128;
    const int n0 = blockIdx.y * 64;

    if (blockIdx.x == 0 && blockIdx.y == 0 && blockIdx.z == 0 && threadIdx.x == 0)
        g_cnt = 0u;   // per-launch barrier reset (graph-replay safe)

    __shared__ __align__(16) float As[16][132];
    __shared__ __align__(16) float Bs[16][68];

    const int tid = threadIdx.x;
    const int tx  = tid & 15;
    const int ty  = tid >> 4;

    float acc[8][4];
#pragma unroll
    for (int i = 0; i < 8; i++)
#pragma unroll
        for (int j = 0; j < 4; j++) acc[i][j] = 0.f;

    for (int k0 = 0; k0 < HDIM; k0 += 16) {
#pragma unroll
        for (int i = 0; i < 2; i++) {
            int idx = tid * 2 + i;
            int row = idx >> 2;
            int c4  = idx & 3;
            float4 v = *reinterpret_cast<const float4*>(x + (size_t)(m0 + row) * HDIM + k0 + c4 * 4);
            As[c4 * 4 + 0][row] = v.x;
            As[c4 * 4 + 1][row] = v.y;
            As[c4 * 4 + 2][row] = v.z;
            As[c4 * 4 + 3][row] = v.w;
        }
        {
            int row = tid >> 2;
            int c4  = tid & 3;
            float4 v = *reinterpret_cast<const float4*>(Bmat + (size_t)(n0 + row) * HDIM + k0 + c4 * 4);
            Bs[c4 * 4 + 0][row] = v.x;
            Bs[c4 * 4 + 1][row] = v.y;
            Bs[c4 * 4 + 2][row] = v.z;
            Bs[c4 * 4 + 3][row] = v.w;
        }
        __syncthreads();

#pragma unroll
        for (int k = 0; k < 16; k++) {
            float a[8], b[4];
#pragma unroll
            for (int i = 0; i < 8; i++) a[i] = As[k][ty * 8 + i];
#pragma unroll
            for (int j = 0; j < 4; j++) b[j] = Bs[k][tx * 4 + j];
#pragma unroll
            for (int i = 0; i < 8; i++)
#pragma unroll
                for (int j = 0; j < 4; j++) acc[i][j] = fmaf(a[i], b[j], acc[i][j]);
        }
        __syncthreads();
    }

    float4 bv = *reinterpret_cast<const float4*>(bias + n0 + tx * 4);
#pragma unroll
    for (int i = 0; i < 8; i++) {
        float4 o;
        o.x = acc[i][0] + bv.x;
        o.y = acc[i][1] + bv.y;
        o.z = acc[i][2] + bv.z;
        o.w = acc[i][3] + bv.w;
        *reinterpret_cast<float4*>(C + (size_t)(m0 + ty * 8 + i) * HDIM + n0 + tx * 4) = o;
    }
}

// ---------------- helpers ----------------
__device__ __forceinline__ float sigmoidf_(float v) {
    return 1.f / (1.f + __expf(-v));
}
__device__ __forceinline__ u64 pack2(float lo, float hi) {
    u64 r;
    asm("mov.b64 %0, {%1, %2};" : "=l"(r) : "r"(__float_as_uint(lo)), "r"(__float_as_uint(hi)));
    return r;
}
__device__ __forceinline__ float sum2(u64 v) {
    unsigned lo, hi;
    asm("mov.b64 {%0, %1}, %2;" : "=r"(lo), "=r"(hi) : "l"(v));
    return __uint_as_float(lo) + __uint_as_float(hi);
}
__device__ __forceinline__ void ffma2(u64& d, u64 a, u64 b) {
    asm("fma.rn.f32x2 %0, %1, %2, %0;" : "+l"(d) : "l"(a), "l"(b));
}

// ---------------- colmin: partial column-mins of XPu over t in [1, T) ----------------
__global__ __launch_bounds__(256) void colmin_kernel() {
    const int tid = threadIdx.x;
    const float* __restrict__ XPu = g_XP[0];
    const float INF = __int_as_float(0x7f800000);
    float4 m = make_float4(INF, INF, INF, INF);
    for (int t = 1 + blockIdx.x; t < T_SEQ; t += gridDim.x) {
        float4 v = *reinterpret_cast<const float4*>(XPu + (size_t)t * HDIM + 4 * tid);
        m.x = fminf(m.x, v.x);
        m.y = fminf(m.y, v.y);
        m.z = fminf(m.z, v.z);
        m.w = fminf(m.w, v.w);
    }
    *reinterpret_cast<float4*>(&g_pmin[blockIdx.x][4 * tid]) = m;
}

// ---------------- check: h1, su = Wu@h1, verify saturation bound ----------------
// Sufficient condition for outputs[t] == h1 (within 8192*e^-20 ~ 1.7e-5 << 1e-3):
//   for every row r:  min_{t>=1} xu[t,r] + (Wu @ h1)_r >= 20
// Then (1-u_t) <= e^-20 for all t>=1, so the reference's h drifts by <= 1.7e-5 total.
__global__ __launch_bounds__(256) void check_kernel(const float* __restrict__ Wu) {
    __shared__ __align__(16) float h1s[HDIM];
    const int tid = threadIdx.x;
    const float INF = __int_as_float(0x7f800000);

    // h1 for rows 4*tid..4*tid+3 (elementwise; step 0 has h=0 so su=sr=sc=0).
    float4 au = *reinterpret_cast<const float4*>(g_XP[0] + 4 * tid);
    float4 ac = *reinterpret_cast<const float4*>(g_XP[2] + 4 * tid);
    float4 h1;
    {
        float u, cd;
        u = sigmoidf_(au.x); cd = sigmoidf_(ac.x); h1.x = fmaf(u, 0.f - cd, cd);
        u = sigmoidf_(au.y); cd = sigmoidf_(ac.y); h1.y = fmaf(u, 0.f - cd, cd);
        u = sigmoidf_(au.z); cd = sigmoidf_(ac.z); h1.z = fmaf(u, 0.f - cd, cd);
        u = sigmoidf_(au.w); cd = sigmoidf_(ac.w); h1.w = fmaf(u, 0.f - cd, cd);
    }
    *reinterpret_cast<float4*>(h1s + 4 * tid) = h1;
    *reinterpret_cast<float4*>(g_h1 + 4 * tid) = h1;
    __syncthreads();

    int ok = 1;
#pragma unroll 1
    for (int rr = 0; rr < 4; rr++) {
        int r = tid + rr * 256;
        // su_r = Wu[r] . h1  (smem broadcast reads, 4 partial chains for ILP)
        const float* wrow = Wu + (size_t)r * HDIM;
        float s0 = 0.f, s1 = 0.f, s2 = 0.f, s3 = 0.f;
#pragma unroll 8
        for (int k = 0; k < HDIM; k += 4) {
            float4 wv = *reinterpret_cast<const float4*>(wrow + k);
            s0 = fmaf(wv.x, h1s[k + 0], s0);
            s1 = fmaf(wv.y, h1s[k + 1], s1);
            s2 = fmaf(wv.z, h1s[k + 2], s2);
            s3 = fmaf(wv.w, h1s[k + 3], s3);
        }
        float su = (s0 + s1) + (s2 + s3);
        // column min over all CTA partials (coalesced across threads)
        float m = INF;
#pragma unroll 8
        for (int i = 0; i < NBLK; i++) m = fminf(m, g_pmin[i][r]);
        if (!(m + su >= 20.0f)) ok = 0;
    }
    int all = __syncthreads_and(ok);
    if (tid == 0) g_fast = all;
}

// ---------------- fill: outputs[t] = h1 for all t, h_final = h1 (fast path) ----------------
__global__ __launch_bounds__(256) void fill_kernel(float* __restrict__ out) {
    if (!g_fast) return;
    const int tid = threadIdx.x;
    float4 v = *reinterpret_cast<const float4*>(g_h1 + 4 * tid);
    float4* outp = reinterpret_cast<float4*>(out + HDIM);
#pragma unroll 1
    for (int t = blockIdx.x; t < T_SEQ; t += gridDim.x)
        outp[(size_t)t * 256 + tid] = v;
    if (blockIdx.x == 0)
        reinterpret_cast<float4*>(out)[tid] = v;
}

// ---------------- fallback scan (R9-proven; early-exits on fast path) ----------------
__global__ __launch_bounds__(256, 1) void scan_kernel(
    const float* __restrict__ Wu, const float* __restrict__ Wr, const float* __restrict__ Wc,
    float* __restrict__ out)
{
    if (*(volatile int*)&g_fast) return;   // uniform: fast path already wrote out

    __shared__ __align__(16) float hs[HDIM];

    const int tid = threadIdx.x;
    const int l   = tid & 31;
    const int w   = tid >> 5;
    const int r   = blockIdx.x * 8 + w;

    u64 wu2[16], wr2[16], wc2[16];
#pragma unroll
    for (int j = 0; j < 16; j++) {
        int c = j * 64 + 2 * l;
        float2 a = *reinterpret_cast<const float2*>(Wu + (size_t)r * HDIM + c);
        float2 b = *reinterpret_cast<const float2*>(Wr + (size_t)r * HDIM + c);
        float2 d = *reinterpret_cast<const float2*>(Wc + (size_t)r * HDIM + c);
        wu2[j] = pack2(a.x, a.y);
        wr2[j] = pack2(b.x, b.y);
        wc2[j] = pack2(d.x, d.y);
    }

    const float* __restrict__ XPu = g_XP[0];
    const float* __restrict__ XPr = g_XP[1];
    const float* __restrict__ XPc = g_XP[2];

    float au = 0.f, ar = 0.f, ac = 0.f;
    if (l == 0) {
        au = __ldcg(XPu + r);
        ar = __ldcg(XPr + r);
        ac = __ldcg(XPc + r);
    }

    unsigned target = 0;

#pragma unroll 1
    for (int t = 0; t < T_SEQ; ++t) {
        float* hout = g_hbuf[(t + 1) & 1];

        if (t == 0) {
            reinterpret_cast<float4*>(hs)[tid] = make_float4(0.f, 0.f, 0.f, 0.f);
        } else {
            const float* hin = g_hbuf[t & 1];
            float4 hv4 = __ldcg(reinterpret_cast<const float4*>(hin) + tid);
            reinterpret_cast<float4*>(hs)[tid] = hv4;
        }
        __syncthreads();

        float aun = 0.f, arn = 0.f, acn = 0.f;
        if (l == 0) {
            int tn = (t + 1 < T_SEQ) ? (t + 1) : t;
            size_t off = (size_t)tn * HDIM + r;
            aun = __ldcg(XPu + off);
            arn = __ldcg(XPr + off);
            acn = __ldcg(XPc + off);
        }

        u64 su2 = 0, sr2 = 0, sc2 = 0;
#pragma unroll
        for (int j = 0; j < 16; j++) {
            u64 hp = *reinterpret_cast<const u64*>(hs + j * 64 + 2 * l);
            ffma2(su2, wu2[j], hp);
            ffma2(sr2, wr2[j], hp);
            ffma2(sc2, wc2[j], hp);
        }
        float su = sum2(su2), sr = sum2(sr2), sc = sum2(sc2);
#pragma unroll
        for (int off = 16; off > 0; off >>= 1) {
            su += __shfl_down_sync(0xffffffffu, su, off);
            sr += __shfl_down_sync(0xffffffffu, sr, off);
            sc += __shfl_down_sync(0xffffffffu, sc, off);
        }

        if (l == 0) {
            float hprev = hs[r];
            float u  = sigmoidf_(au + su);
            float rg = sigmoidf_(ar + sr);
            float cd = sigmoidf_(ac + rg * sc);
            float hn = fmaf(u, hprev - cd, cd);
            __stcg(hout + r, hn);
            out[HDIM + (size_t)t * HDIM + r] = hn;
            if (t == T_SEQ - 1) out[r] = hn;
        }
        au = aun; ar = arn; ac = acn;

        __syncthreads();
        if (tid == 0) {
            __threadfence();
            atomicAdd(&g_cnt, 1u);
            target += NBLK;
            while (*((volatile unsigned*)&g_cnt) < target) { }
            __threadfence();
        }
        __syncthreads();
    }
}

// ---------------- launch ----------------
extern "C" void kernel_launch(void* const* d_in, const int* in_sizes, int n_in,
                              void* d_out, int out_size) {
    const float* x  = (const float*)d_in[0];
    const float* Uu = (const float*)d_in[1];
    const float* Wu = (const float*)d_in[2];
    const float* Bu = (const float*)d_in[3];
    const float* Ur = (const float*)d_in[4];
    const float* Wr = (const float*)d_in[5];
    const float* Br = (const float*)d_in[6];
    const float* Uc = (const float*)d_in[7];
    const float* Wc = (const float*)d_in[8];
    const float* Bc = (const float*)d_in[9];
    float* out = (float*)d_out;

    dim3 g(T_SEQ / 128, HDIM / 64, 3);
    proj_gemm<<<g, 256>>>(x, Uu, Ur, Uc, Bu, Br, Bc);

    colmin_kernel<<<NBLK, 256>>>();
    check_kernel<<<1, 256>>>(Wu);
    fill_kernel<<<256, 256>>>(out);
    scan_kernel<<<NBLK, 256>>>(Wu, Wr, Wc, out);
}